// round 7
// baseline (speedup 1.0000x reference)
#include <cuda_runtime.h>
#include <cuda_bf16.h>
#include <cstdint>

#define DIM 256
#define NBINS 32
#define CT 32            // columns per tile (block)
#define MINW 1e-3f
#define MINH 1e-3f
#define MIND 1e-3f

__device__ __forceinline__ float softplus_min(float v) {
    float sp = (v > 15.f) ? v : log1pf(expf(v));
    return MIND + sp;
}

// Fused kernel: each block builds the spline tables for its 32-column tile in
// shared memory (warp-parallel softmax/scan), then streams rows through it.
__global__ void __launch_bounds__(256, 8)
spline_fused_kernel(const float* __restrict__ x,
                    const float* __restrict__ width,
                    const float* __restrict__ height,
                    const float* __restrict__ deriv,
                    float* __restrict__ out, int B) {
    __shared__ float4 s_pA[CT * NBINS];   // {cw_lo, 1/w, ch_lo, h}  16 KB
    __shared__ float2 s_pB[CT * NBINS];   // {d0, d1}                 8 KB

    const int colBase = blockIdx.y * CT;
    const int tid = threadIdx.x;
    const int wp  = tid >> 5;     // warp 0..7
    const int l   = tid & 31;     // lane

    // ---- fused precompute: warp wp handles local columns wp, wp+8, wp+16, wp+24
    #pragma unroll
    for (int rep = 0; rep < 4; rep++) {
        const int lc = wp + rep * 8;
        const int g  = colBase + lc;

        // widths: softmax -> floor -> cumsum
        float wv = width[g * NBINS + l];
        float m = wv;
        #pragma unroll
        for (int o = 16; o; o >>= 1) m = fmaxf(m, __shfl_xor_sync(0xFFFFFFFFu, m, o));
        float e = __expf(wv - m);
        float s = e;
        #pragma unroll
        for (int o = 16; o; o >>= 1) s += __shfl_xor_sync(0xFFFFFFFFu, s, o);
        float sz = MINW + (1.f - NBINS * MINW) * (e / s);
        float incl = sz;
        #pragma unroll
        for (int o = 1; o < 32; o <<= 1) {
            float v = __shfl_up_sync(0xFFFFFFFFu, incl, o);
            if (l >= o) incl += v;
        }
        float cw_hi = (l == 31) ? 1.f : incl;
        float up = __shfl_up_sync(0xFFFFFFFFu, incl, 1);
        float cw_lo = (l == 0) ? 0.f : up;
        float w = cw_hi - cw_lo;

        // heights
        float hv = height[g * NBINS + l];
        float mh = hv;
        #pragma unroll
        for (int o = 16; o; o >>= 1) mh = fmaxf(mh, __shfl_xor_sync(0xFFFFFFFFu, mh, o));
        float eh = __expf(hv - mh);
        float sh = eh;
        #pragma unroll
        for (int o = 16; o; o >>= 1) sh += __shfl_xor_sync(0xFFFFFFFFu, sh, o);
        float szh = MINH + (1.f - NBINS * MINH) * (eh / sh);
        float inclh = szh;
        #pragma unroll
        for (int o = 1; o < 32; o <<= 1) {
            float v = __shfl_up_sync(0xFFFFFFFFu, inclh, o);
            if (l >= o) inclh += v;
        }
        float ch_hi = (l == 31) ? 1.f : inclh;
        float uph = __shfl_up_sync(0xFFFFFFFFu, inclh, 1);
        float ch_lo = (l == 0) ? 0.f : uph;
        float h = ch_hi - ch_lo;

        // derivatives: lane l loads deriv[l] (interior), shfl_up gives d0
        float sp = (l < NBINS - 1) ? softplus_min(deriv[g * (NBINS - 1) + l]) : 1.f;
        float d1 = (l == NBINS - 1) ? 1.f : sp;
        float spp = __shfl_up_sync(0xFFFFFFFFu, sp, 1);
        float d0 = (l == 0) ? 1.f : spp;

        s_pA[lc * NBINS + l] = make_float4(cw_lo, 1.f / w, ch_lo, h);
        s_pB[lc * NBINS + l] = make_float2(d0, d1);
    }
    __syncthreads();

    // ---- main streaming loop
    const int cg   = tid & 7;     // colgroup 0..7 (4 cols each)
    const int rown = tid >> 3;    // 0..31
    const int lc0  = cg * 4;
    const int colOff = colBase + lc0;

    float* __restrict__ outY = out;
    float* __restrict__ outL = out + (size_t)B * DIM;

    for (int row = blockIdx.x * 32 + rown; row < B; row += gridDim.x * 32) {
        const float4 xv = *(const float4*)(x + (size_t)row * DIM + colOff);
        float yv[4], lv[4];
        #pragma unroll
        for (int k = 0; k < 4; k++) {
            const int lc = lc0 + k;
            const float4* __restrict__ colA = s_pA + lc * NBINS;
            float xs = (k == 0) ? xv.x : (k == 1) ? xv.y : (k == 2) ? xv.z : xv.w;
            float xc = fminf(fmaxf(xs, 0.f), 1.f);

            // uniform guess + 2 branchless predicated corrections + rare safety loop
            int b = __float2int_rd(xc * 32.f);
            b = (b > NBINS - 1) ? NBINS - 1 : b;
            float4 pa = colA[b];
            float theta = (xc - pa.x) * pa.y;
            #pragma unroll
            for (int it = 0; it < 2; ++it) {
                int nb = b + ((theta >= 1.f) ? 1 : 0) - ((theta < 0.f) ? 1 : 0);
                nb = (nb < 0) ? 0 : (nb > NBINS - 1 ? NBINS - 1 : nb);
                if (nb != b) {
                    b = nb; pa = colA[b]; theta = (xc - pa.x) * pa.y;
                }
            }
            while ((theta < 0.f && b > 0) || (theta >= 1.f && b < NBINS - 1)) {
                b += (theta >= 1.f) ? 1 : -1;
                pa = colA[b]; theta = (xc - pa.x) * pa.y;
            }

            const float2 pb = s_pB[lc * NBINS + b];

            float omt    = 1.f - theta;
            float t1m    = theta * omt;
            float th2    = theta * theta;
            float h      = pa.w;
            float delta  = h * pa.y;        // h * invw
            float delta2 = delta * delta;
            float dd0 = pb.x, dd1 = pb.y;

            float num  = h * fmaf(delta, th2, dd0 * t1m);
            float den  = fmaf(dd0 + dd1 - 2.f * delta, t1m, delta);
            float rden = __fdividef(1.f, den);
            float yin  = fmaf(num, rden, pa.z);

            float dnum = delta2 * fmaf(dd1, th2, fmaf(2.f * delta, t1m, dd0 * omt * omt));
            float lin  = __logf(dnum * rden * rden);

            bool inside = (xs >= 0.f) && (xs <= 1.f);
            yv[k] = inside ? yin : xs;
            lv[k] = inside ? lin : 0.f;
        }
        *(float4*)(outY + (size_t)row * DIM + colOff) = make_float4(yv[0], yv[1], yv[2], yv[3]);
        *(float4*)(outL + (size_t)row * DIM + colOff) = make_float4(lv[0], lv[1], lv[2], lv[3]);
    }
}

extern "C" void kernel_launch(void* const* d_in, const int* in_sizes, int n_in,
                              void* d_out, int out_size) {
    const float* x      = (const float*)d_in[0];
    const float* width  = (const float*)d_in[1];
    const float* height = (const float*)d_in[2];
    const float* deriv  = (const float*)d_in[3];
    float* out = (float*)d_out;

    const int B = in_sizes[0] / DIM;

    dim3 grid(148, DIM / CT);   // 1184 blocks = 148 SMs x 8 blocks (full thread wave)
    spline_fused_kernel<<<grid, 256>>>(x, width, height, deriv, out, B);
}

// round 11
// speedup vs baseline: 1.2394x; 1.2394x over previous
#include <cuda_runtime.h>
#include <cuda_bf16.h>
#include <cstdint>

#define DIM 256
#define NBINS 32
#define CT 32            // columns per tile
#define MINW 1e-3f
#define MINH 1e-3f
#define MIND 1e-3f

// Precomputed per-(dim,bin) tables, split into float2 to reduce LDS bank conflicts
__device__ float2 g_p0[DIM * NBINS];   // {cw_lo, 1/w}
__device__ float2 g_p1[DIM * NBINS];   // {ch_lo, h}
__device__ float2 g_p2[DIM * NBINS];   // {d0, d1}

__device__ __forceinline__ float softplus_min(float v) {
    float sp = (v > 15.f) ? v : log1pf(expf(v));
    return MIND + sp;
}

// One warp per dim: softmax -> floor -> cumsum for widths & heights, derivatives.
__global__ void spline_precompute_kernel(const float* __restrict__ width,
                                         const float* __restrict__ height,
                                         const float* __restrict__ deriv) {
    int d = blockIdx.x;
    int t = threadIdx.x;   // 0..31

    // ---- widths ----
    float wv = width[d * NBINS + t];
    float m = wv;
    #pragma unroll
    for (int o = 16; o; o >>= 1) m = fmaxf(m, __shfl_xor_sync(0xFFFFFFFFu, m, o));
    float e = __expf(wv - m);
    float s = e;
    #pragma unroll
    for (int o = 16; o; o >>= 1) s += __shfl_xor_sync(0xFFFFFFFFu, s, o);
    float sz = MINW + (1.f - NBINS * MINW) * (e / s);
    float incl = sz;
    #pragma unroll
    for (int o = 1; o < 32; o <<= 1) {
        float v = __shfl_up_sync(0xFFFFFFFFu, incl, o);
        if (t >= o) incl += v;
    }
    float cw_hi = (t == 31) ? 1.f : incl;
    float up = __shfl_up_sync(0xFFFFFFFFu, incl, 1);
    float cw_lo = (t == 0) ? 0.f : up;
    float w = cw_hi - cw_lo;

    // ---- heights ----
    float hv = height[d * NBINS + t];
    float mh = hv;
    #pragma unroll
    for (int o = 16; o; o >>= 1) mh = fmaxf(mh, __shfl_xor_sync(0xFFFFFFFFu, mh, o));
    float eh = __expf(hv - mh);
    float sh = eh;
    #pragma unroll
    for (int o = 16; o; o >>= 1) sh += __shfl_xor_sync(0xFFFFFFFFu, sh, o);
    float szh = MINH + (1.f - NBINS * MINH) * (eh / sh);
    float inclh = szh;
    #pragma unroll
    for (int o = 1; o < 32; o <<= 1) {
        float v = __shfl_up_sync(0xFFFFFFFFu, inclh, o);
        if (t >= o) inclh += v;
    }
    float ch_hi = (t == 31) ? 1.f : inclh;
    float uph = __shfl_up_sync(0xFFFFFFFFu, inclh, 1);
    float ch_lo = (t == 0) ? 0.f : uph;
    float h = ch_hi - ch_lo;

    // ---- derivatives (boundary == 1 exactly) ----
    float d0 = (t == 0)  ? 1.f : softplus_min(deriv[d * (NBINS - 1) + t - 1]);
    float d1 = (t == 31) ? 1.f : softplus_min(deriv[d * (NBINS - 1) + t]);

    float invw = 1.f / w;

    g_p0[d * NBINS + t] = make_float2(cw_lo, invw);
    g_p1[d * NBINS + t] = make_float2(ch_lo, h);
    g_p2[d * NBINS + t] = make_float2(d0, d1);
}

// Main kernel: each block owns a 32-column tile; tables live in smem as three
// float2 arrays (8B stride -> b mod 16 bank groups, ~half the conflicts of float4).
__global__ void __launch_bounds__(256, 8)
spline_main_kernel(const float* __restrict__ x, float* __restrict__ out, int B) {
    __shared__ float2 s_p0[CT * NBINS];   // 8 KB {cw_lo, invw}
    __shared__ float2 s_p1[CT * NBINS];   // 8 KB {ch_lo, h}
    __shared__ float2 s_p2[CT * NBINS];   // 8 KB {d0, d1}

    const int colBase = blockIdx.y * CT;
    const int tid = threadIdx.x;

    for (int i = tid; i < CT * NBINS; i += 256) {
        s_p0[i] = g_p0[colBase * NBINS + i];
        s_p1[i] = g_p1[colBase * NBINS + i];
        s_p2[i] = g_p2[colBase * NBINS + i];
    }
    __syncthreads();

    const int cg   = tid & 7;     // colgroup 0..7 (4 cols each)
    const int rown = tid >> 3;    // 0..31
    const int lc0  = cg * 4;
    const int colOff = colBase + lc0;

    float* __restrict__ outY = out;
    float* __restrict__ outL = out + (size_t)B * DIM;

    for (int row = blockIdx.x * 32 + rown; row < B; row += gridDim.x * 32) {
        const float4 xv = *(const float4*)(x + (size_t)row * DIM + colOff);
        float yv[4], lv[4];
        #pragma unroll
        for (int k = 0; k < 4; k++) {
            const int lc = lc0 + k;
            const float2* __restrict__ col0 = s_p0 + lc * NBINS;
            float xs = (k == 0) ? xv.x : (k == 1) ? xv.y : (k == 2) ? xv.z : xv.w;
            float xc = fminf(fmaxf(xs, 0.f), 1.f);

            // uniform guess + gather-retry on the 8B {cw_lo, invw} table only
            int b = __float2int_rd(xc * 32.f);
            b = (b > NBINS - 1) ? NBINS - 1 : b;
            float2 p0 = col0[b];
            float theta = (xc - p0.x) * p0.y;
            while (theta < 0.f && b > 0) {
                --b; p0 = col0[b]; theta = (xc - p0.x) * p0.y;
            }
            while (theta >= 1.f && b < NBINS - 1) {
                ++b; p0 = col0[b]; theta = (xc - p0.x) * p0.y;
            }

            const float2 p1 = s_p1[lc * NBINS + b];
            const float2 p2 = s_p2[lc * NBINS + b];

            float omt    = 1.f - theta;
            float t1m    = theta * omt;
            float th2    = theta * theta;
            float h      = p1.y;
            float delta  = h * p0.y;        // h * invw
            float delta2 = delta * delta;
            float dd0 = p2.x, dd1 = p2.y;

            float num  = h * fmaf(delta, th2, dd0 * t1m);
            float den  = fmaf(dd0 + dd1 - 2.f * delta, t1m, delta);
            float rden = __fdividef(1.f, den);
            float yin  = fmaf(num, rden, p1.x);

            float dnum = delta2 * fmaf(dd1, th2, fmaf(2.f * delta, t1m, dd0 * omt * omt));
            float lin  = __logf(dnum * rden * rden);

            bool inside = (xs >= 0.f) && (xs <= 1.f);
            yv[k] = inside ? yin : xs;
            lv[k] = inside ? lin : 0.f;
        }
        *(float4*)(outY + (size_t)row * DIM + colOff) = make_float4(yv[0], yv[1], yv[2], yv[3]);
        *(float4*)(outL + (size_t)row * DIM + colOff) = make_float4(lv[0], lv[1], lv[2], lv[3]);
    }
}

extern "C" void kernel_launch(void* const* d_in, const int* in_sizes, int n_in,
                              void* d_out, int out_size) {
    const float* x      = (const float*)d_in[0];
    const float* width  = (const float*)d_in[1];
    const float* height = (const float*)d_in[2];
    const float* deriv  = (const float*)d_in[3];
    float* out = (float*)d_out;

    const int B = in_sizes[0] / DIM;

    spline_precompute_kernel<<<DIM, 32>>>(width, height, deriv);

    dim3 grid(148, DIM / CT);   // 1184 blocks = 148 SMs x 8 blocks (full thread wave)
    spline_main_kernel<<<grid, 256>>>(x, out, B);
}